// round 3
// baseline (speedup 1.0000x reference)
#include <cuda_runtime.h>
#include <math.h>

#define N1 16384
#define N2 16384
#define NSL 16
#define SL (N2 / NSL)        // 1024 points per slice
#define TPB 128
#define QPT 2
#define QPB (TPB * QPT)      // 256 queries per block
#define QBLK (N1 / QPB)      // 64 query blocks
#define RBLK (N1 / 256)      // 64 combine blocks

// Scratch (no allocations allowed -> __device__ globals)
__device__ float g_xs[N2];
__device__ float g_ys[N2];
__device__ float g_ss[N2];
__device__ float g_partial[NSL * N1];
__device__ float g_bsum[RBLK];

typedef unsigned long long u64;

__device__ __forceinline__ u64 pack2(float a, float b) {
    u64 r;
    asm("mov.b64 %0, {%1, %2};" : "=l"(r) : "f"(a), "f"(b));
    return r;
}
__device__ __forceinline__ u64 fma2(u64 a, u64 b, u64 c) {
    u64 d;
    asm("fma.rn.f32x2 %0, %1, %2, %3;" : "=l"(d) : "l"(a), "l"(b), "l"(c));
    return d;
}
__device__ __forceinline__ void unpack2(u64 v, float& lo, float& hi) {
    asm("mov.b64 {%0, %1}, %2;" : "=f"(lo), "=f"(hi) : "l"(v));
}

// Convert pos2 AoS -> SoA (x, y, x^2+y^2)
__global__ void prep_kernel(const float* __restrict__ pos2) {
    int i = blockIdx.x * blockDim.x + threadIdx.x;
    if (i < N2) {
        float x = pos2[2 * i];
        float y = pos2[2 * i + 1];
        g_xs[i] = x;
        g_ys[i] = y;
        g_ss[i] = x * x + y * y;
    }
}

// For each query q and slice sl: min over p in slice of (|p|^2 - 2 q.p)
__global__ void __launch_bounds__(TPB) slice_kernel(const float* __restrict__ pos1) {
    __shared__ __align__(16) float sx[SL];
    __shared__ __align__(16) float sy[SL];
    __shared__ __align__(16) float ss[SL];

    const int sl = blockIdx.y;
    const int base = sl * SL;
    for (int i = threadIdx.x; i < SL; i += TPB) {
        sx[i] = g_xs[base + i];
        sy[i] = g_ys[base + i];
        ss[i] = g_ss[base + i];
    }
    __syncthreads();

    const int q0 = blockIdx.x * QPB + threadIdx.x;
    const int q1 = q0 + TPB;

    const float nx0 = -2.0f * pos1[2 * q0];
    const float ny0 = -2.0f * pos1[2 * q0 + 1];
    const float nx1 = -2.0f * pos1[2 * q1];
    const float ny1 = -2.0f * pos1[2 * q1 + 1];

    const u64 px0 = pack2(nx0, nx0), py0 = pack2(ny0, ny0);
    const u64 px1 = pack2(nx1, nx1), py1 = pack2(ny1, ny1);

    float m00 = 3.0e38f, m01 = 3.0e38f;   // query 0: lo/hi chains
    float m10 = 3.0e38f, m11 = 3.0e38f;   // query 1

    const ulonglong2* __restrict__ XV = (const ulonglong2*)sx;
    const ulonglong2* __restrict__ YV = (const ulonglong2*)sy;
    const ulonglong2* __restrict__ SV = (const ulonglong2*)ss;

    #pragma unroll 4
    for (int j = 0; j < SL / 4; j++) {
        ulonglong2 X = XV[j];   // 4 x-coords as two packed f32x2
        ulonglong2 Y = YV[j];
        ulonglong2 S = SV[j];
        float lo, hi;
        u64 t;

        // query 0, points j*4 .. j*4+3
        t = fma2(py0, Y.x, S.x); t = fma2(px0, X.x, t);
        unpack2(t, lo, hi); m00 = fminf(m00, lo); m01 = fminf(m01, hi);
        t = fma2(py0, Y.y, S.y); t = fma2(px0, X.y, t);
        unpack2(t, lo, hi); m00 = fminf(m00, lo); m01 = fminf(m01, hi);

        // query 1
        t = fma2(py1, Y.x, S.x); t = fma2(px1, X.x, t);
        unpack2(t, lo, hi); m10 = fminf(m10, lo); m11 = fminf(m11, hi);
        t = fma2(py1, Y.y, S.y); t = fma2(px1, X.y, t);
        unpack2(t, lo, hi); m10 = fminf(m10, lo); m11 = fminf(m11, hi);
    }

    g_partial[sl * N1 + q0] = fminf(m00, m01);
    g_partial[sl * N1 + q1] = fminf(m10, m11);
}

// Combine slices -> nearest distance per query -> per-block sum (deterministic tree)
__global__ void __launch_bounds__(256) combine_kernel(const float* __restrict__ pos1) {
    const int q = blockIdx.x * 256 + threadIdx.x;
    float m = 3.0e38f;
    #pragma unroll
    for (int s = 0; s < NSL; s++) m = fminf(m, g_partial[s * N1 + q]);
    const float x = pos1[2 * q];
    const float y = pos1[2 * q + 1];
    const float d2 = fmaxf(m + x * x + y * y, 0.0f);
    const float d = sqrtf(d2);

    __shared__ float red[256];
    red[threadIdx.x] = d;
    __syncthreads();
    #pragma unroll
    for (int s = 128; s > 0; s >>= 1) {
        if (threadIdx.x < s) red[threadIdx.x] += red[threadIdx.x + s];
        __syncthreads();
    }
    if (threadIdx.x == 0) g_bsum[blockIdx.x] = red[0];
}

__global__ void final_kernel(float* __restrict__ out) {
    __shared__ float red[RBLK];
    red[threadIdx.x] = g_bsum[threadIdx.x];
    __syncthreads();
    #pragma unroll
    for (int s = RBLK / 2; s > 0; s >>= 1) {
        if (threadIdx.x < s) red[threadIdx.x] += red[threadIdx.x + s];
        __syncthreads();
    }
    if (threadIdx.x == 0) out[0] = red[0] * (1.0f / (float)N1);
}

extern "C" void kernel_launch(void* const* d_in, const int* in_sizes, int n_in,
                              void* d_out, int out_size) {
    const float* pos1 = (const float*)d_in[0];
    const float* pos2 = (const float*)d_in[1];

    prep_kernel<<<N2 / 256, 256>>>(pos2);
    dim3 grid(QBLK, NSL);
    slice_kernel<<<grid, TPB>>>(pos1);
    combine_kernel<<<RBLK, 256>>>(pos1);
    final_kernel<<<1, RBLK>>>((float*)d_out);
}